// round 2
// baseline (speedup 1.0000x reference)
#include <cuda_runtime.h>
#include <cstddef>

// LimbLength: out[b][k] = || in[b][k][:] - in[b][conn[k]][:] ||_2
// B = in_sizes[0]/45 samples, 15 joints x 3 coords each.
//
// HBM-bound: stage 256 samples (256*45 floats) into shared memory with
// coalesced float4 loads, compute per-thread, then REUSE the same smem buffer
// for the 256*15 outputs (keeps static smem = 46080 B < 48 KB limit), and
// write back with coalesced float4 stores.

#define SPB 256   // samples per block
#define TPB 256   // threads per block

__global__ void __launch_bounds__(TPB, 3)
limb_length_kernel(const float* __restrict__ in, float* __restrict__ out, int B) {
    __shared__ float s_buf[SPB * 45];   // 46080 B — reused for input then output

    const int base = blockIdx.x * SPB;
    if (base >= B) return;
    const int nsamp = min(SPB, B - base);

    // ---- coalesced load: gmem -> smem (float4 bulk + scalar remainder) ----
    {
        const size_t goff = (size_t)base * 45;
        const int nfloat = nsamp * 45;
        const int n4 = nfloat >> 2;
        const float4* __restrict__ g4 = reinterpret_cast<const float4*>(in + goff);
        float4* s4 = reinterpret_cast<float4*>(s_buf);
        for (int i = threadIdx.x; i < n4; i += TPB) s4[i] = g4[i];
        for (int i = (n4 << 2) + threadIdx.x; i < nfloat; i += TPB)
            s_buf[i] = in[goff + i];
    }
    __syncthreads();

    // ---- per-thread compute into registers ----
    float r[15];
    if ((int)threadIdx.x < nsamp) {
        const float* __restrict__ p = s_buf + threadIdx.x * 45;  // stride 45 (odd) -> conflict-free
        float x[15], y[15], z[15];
        #pragma unroll
        for (int k = 0; k < 15; k++) {
            x[k] = p[3 * k + 0];
            y[k] = p[3 * k + 1];
            z[k] = p[3 * k + 2];
        }
        const int conn[15] = {0, 0, 1, 1, 1, 3, 4, 5, 6, 2, 2, 9, 10, 11, 12};
        #pragma unroll
        for (int k = 0; k < 15; k++) {
            const int c = conn[k];  // compile-time resolved under full unroll
            const float dx = x[k] - x[c];
            const float dy = y[k] - y[c];
            const float dz = z[k] - z[c];
            r[k] = sqrtf(dx * dx + dy * dy + dz * dz);
        }
    }
    __syncthreads();   // everyone done reading s_buf before we overwrite it

    // ---- write results into (reused) smem at stride 15 (odd -> conflict-free) ----
    if ((int)threadIdx.x < nsamp) {
        float* q = s_buf + threadIdx.x * 15;
        #pragma unroll
        for (int k = 0; k < 15; k++) q[k] = r[k];
    }
    __syncthreads();

    // ---- coalesced store: smem -> gmem ----
    {
        const size_t goff = (size_t)base * 15;
        const int nfloat = nsamp * 15;
        const int n4 = nfloat >> 2;
        float4* __restrict__ g4 = reinterpret_cast<float4*>(out + goff);
        const float4* s4 = reinterpret_cast<const float4*>(s_buf);
        for (int i = threadIdx.x; i < n4; i += TPB) g4[i] = s4[i];
        for (int i = (n4 << 2) + threadIdx.x; i < nfloat; i += TPB)
            out[goff + i] = s_buf[i];
    }
}

extern "C" void kernel_launch(void* const* d_in, const int* in_sizes, int n_in,
                              void* d_out, int out_size) {
    const float* in = (const float*)d_in[0];
    float* out = (float*)d_out;
    const int B = in_sizes[0] / 45;               // 45 floats per sample
    const int grid = (B + SPB - 1) / SPB;
    limb_length_kernel<<<grid, TPB>>>(in, out, B);
}

// round 3
// speedup vs baseline: 1.0818x; 1.0818x over previous
#include <cuda_runtime.h>
#include <cstddef>

// LimbLength: out[b][k] = || in[b][k][:] - in[b][conn[k]][:] ||_2
// B samples, 15 joints x 3 coords. HBM-bound: maximize occupancy/MLP.
//
// Per block: 128 samples. Coalesced float4 gmem->smem load, per-thread compute
// reading DIRECTLY from smem (keeps regs ~40 -> 10 blocks/SM), results buffered
// in 15 regs, smem buffer reused for coalesced float4 output stores.

#define SPB 128
#define TPB 128

__device__ __forceinline__ float fast_sqrt(float x) {
    float r;
    asm("sqrt.approx.f32 %0, %1;" : "=f"(r) : "f"(x));
    return r;
}

__global__ void __launch_bounds__(TPB, 10)
limb_length_kernel(const float* __restrict__ in, float* __restrict__ out, int B) {
    __shared__ float s_buf[SPB * 45];   // 23040 B, reused for input then output

    const int base = blockIdx.x * SPB;
    if (base >= B) return;
    const int nsamp = min(SPB, B - base);

    // ---- coalesced load: gmem -> smem ----
    {
        const size_t goff = (size_t)base * 45;
        const int nfloat = nsamp * 45;
        const int n4 = nfloat >> 2;
        const float4* __restrict__ g4 = reinterpret_cast<const float4*>(in + goff);
        float4* s4 = reinterpret_cast<float4*>(s_buf);
        #pragma unroll 4
        for (int i = threadIdx.x; i < n4; i += TPB) s4[i] = g4[i];
        for (int i = (n4 << 2) + threadIdx.x; i < nfloat; i += TPB)
            s_buf[i] = in[goff + i];
    }
    __syncthreads();

    // ---- compute directly from smem (stride 45 = odd -> bank-conflict-free) ----
    float r[15];
    if ((int)threadIdx.x < nsamp) {
        const float* __restrict__ p = s_buf + threadIdx.x * 45;
        const int conn[15] = {0, 0, 1, 1, 1, 3, 4, 5, 6, 2, 2, 9, 10, 11, 12};
        #pragma unroll
        for (int k = 0; k < 15; k++) {
            const int c = conn[k];                       // compile-time constant
            const float dx = p[3 * k + 0] - p[3 * c + 0];
            const float dy = p[3 * k + 1] - p[3 * c + 1];
            const float dz = p[3 * k + 2] - p[3 * c + 2];
            r[k] = fast_sqrt(dx * dx + dy * dy + dz * dz);
        }
    }
    __syncthreads();   // all reads of s_buf done before overwrite

    if ((int)threadIdx.x < nsamp) {
        float* q = s_buf + threadIdx.x * 15;             // odd stride -> conflict-free
        #pragma unroll
        for (int k = 0; k < 15; k++) q[k] = r[k];
    }
    __syncthreads();

    // ---- coalesced store: smem -> gmem ----
    {
        const size_t goff = (size_t)base * 15;
        const int nfloat = nsamp * 15;
        const int n4 = nfloat >> 2;
        float4* __restrict__ g4 = reinterpret_cast<float4*>(out + goff);
        const float4* s4 = reinterpret_cast<const float4*>(s_buf);
        #pragma unroll 4
        for (int i = threadIdx.x; i < n4; i += TPB) g4[i] = s4[i];
        for (int i = (n4 << 2) + threadIdx.x; i < nfloat; i += TPB)
            out[goff + i] = s_buf[i];
    }
}

extern "C" void kernel_launch(void* const* d_in, const int* in_sizes, int n_in,
                              void* d_out, int out_size) {
    const float* in = (const float*)d_in[0];
    float* out = (float*)d_out;
    const int B = in_sizes[0] / 45;
    const int grid = (B + SPB - 1) / SPB;
    limb_length_kernel<<<grid, TPB>>>(in, out, B);
}

// round 4
// speedup vs baseline: 1.4292x; 1.3210x over previous
#include <cuda_runtime.h>
#include <cstddef>
#include <cstdint>

// LimbLength: out[b][k] = || in[b][k][:] - in[b][conn[k]][:] ||_2
// Per-WARP tiles of 32 samples: no block barriers at all (only __syncwarp),
// cp.async.cg gmem->smem staging (no register round-trip), compute from smem
// (stride 45/15, odd -> bank-conflict-free), smem reused for coalesced
// float4 output stores.

#define TPB 128
#define WARPS 4
#define SPW 32                      // samples per warp
#define FPW (SPW * 45)              // 1440 floats = 5760 B per warp

__device__ __forceinline__ float fast_sqrt(float x) {
    float r;
    asm("sqrt.approx.f32 %0, %1;" : "=f"(r) : "f"(x));
    return r;
}

__device__ __forceinline__ void cp_async16(uint32_t smem_addr, const void* gptr) {
    asm volatile("cp.async.cg.shared.global [%0], [%1], 16;" ::
                 "r"(smem_addr), "l"(gptr));
}

__global__ void __launch_bounds__(TPB, 9)
limb_length_kernel(const float* __restrict__ in, float* __restrict__ out, int B) {
    __shared__ __align__(16) float s_buf[WARPS * FPW];   // 23040 B

    const int w    = threadIdx.x >> 5;
    const int lane = threadIdx.x & 31;
    const int sbase = (blockIdx.x * WARPS + w) * SPW;    // first sample of this warp
    if (sbase >= B) return;                              // whole warp uniform exit
    const int nsamp = min(SPW, B - sbase);

    float* sw = s_buf + w * FPW;

    // ---- stage gmem -> smem (per-warp, coalesced) ----
    if (nsamp == SPW) {
        // 1440 floats = 360 float4, cp.async 16B each: 11 full rounds + 8 lanes
        const char* gsrc = reinterpret_cast<const char*>(in + (size_t)sbase * 45);
        uint32_t sdst = (uint32_t)__cvta_generic_to_shared(sw);
        #pragma unroll
        for (int j = 0; j < 11; j++) {
            const int i = lane + 32 * j;
            cp_async16(sdst + i * 16, gsrc + i * 16);
        }
        if (lane < 8) {
            const int i = lane + 352;
            cp_async16(sdst + i * 16, gsrc + i * 16);
        }
        asm volatile("cp.async.commit_group;\n"
                     "cp.async.wait_group 0;" ::: "memory");
    } else {
        const size_t goff = (size_t)sbase * 45;
        for (int i = lane; i < nsamp * 45; i += 32) sw[i] = in[goff + i];
    }
    __syncwarp();

    // ---- compute: one sample per lane, straight from smem ----
    float r[15];
    if (lane < nsamp) {
        const float* __restrict__ p = sw + lane * 45;    // stride 45 odd -> conflict-free
        const int conn[15] = {0, 0, 1, 1, 1, 3, 4, 5, 6, 2, 2, 9, 10, 11, 12};
        #pragma unroll
        for (int k = 0; k < 15; k++) {
            const int c = conn[k];                       // compile-time constant
            const float dx = p[3 * k + 0] - p[3 * c + 0];
            const float dy = p[3 * k + 1] - p[3 * c + 1];
            const float dz = p[3 * k + 2] - p[3 * c + 2];
            r[k] = fast_sqrt(dx * dx + dy * dy + dz * dz);
        }
    }
    __syncwarp();                    // all smem reads done before overwrite

    if (lane < nsamp) {
        float* q = sw + lane * 15;                       // stride 15 odd -> conflict-free
        #pragma unroll
        for (int k = 0; k < 15; k++) q[k] = r[k];
    }
    __syncwarp();

    // ---- coalesced store: smem -> gmem (nsamp*15 floats) ----
    {
        const size_t goff = (size_t)sbase * 15;
        const int nfloat = nsamp * 15;
        const int n4 = nfloat >> 2;                      // 120 when full
        float4* __restrict__ g4 = reinterpret_cast<float4*>(out + goff);
        const float4* s4 = reinterpret_cast<const float4*>(sw);
        #pragma unroll 4
        for (int i = lane; i < n4; i += 32) g4[i] = s4[i];
        for (int i = (n4 << 2) + lane; i < nfloat; i += 32)
            out[goff + i] = sw[i];
    }
}

extern "C" void kernel_launch(void* const* d_in, const int* in_sizes, int n_in,
                              void* d_out, int out_size) {
    const float* in = (const float*)d_in[0];
    float* out = (float*)d_out;
    const int B = in_sizes[0] / 45;
    const int spb = WARPS * SPW;     // 128 samples per block
    const int grid = (B + spb - 1) / spb;
    limb_length_kernel<<<grid, TPB>>>(in, out, B);
}

// round 6
// speedup vs baseline: 1.4350x; 1.0041x over previous
#include <cuda_runtime.h>
#include <cstddef>
#include <cstdint>

// LimbLength: out[b][k] = || in[b][k][:] - in[b][conn[k]][:] ||_2
// Per-WARP tiles of 32 samples, no block barriers (only __syncwarp),
// cp.async.cg gmem->smem staging, compute from smem (odd strides 45/15 ->
// bank-conflict-free), smem reused for coalesced float4 output stores.
// 3 warps/block (17,280 B smem) -> 13 blocks/SM = 39 resident warps.

#define TPB 96
#define WARPS 3
#define SPW 32                      // samples per warp
#define FPW (SPW * 45)              // 1440 floats = 5760 B per warp

__device__ __forceinline__ float fast_sqrt(float x) {
    float r;
    asm("sqrt.approx.f32 %0, %1;" : "=f"(r) : "f"(x));
    return r;
}

__device__ __forceinline__ void cp_async16(uint32_t smem_addr, const void* gptr) {
    asm volatile("cp.async.cg.shared.global [%0], [%1], 16;" ::
                 "r"(smem_addr), "l"(gptr));
}

__global__ void __launch_bounds__(TPB, 13)
limb_length_kernel(const float* __restrict__ in, float* __restrict__ out, int B) {
    __shared__ __align__(16) float s_buf[WARPS * FPW];   // 17280 B

    const int w    = threadIdx.x >> 5;
    const int lane = threadIdx.x & 31;
    const int sbase = (blockIdx.x * WARPS + w) * SPW;    // first sample of this warp
    if (sbase >= B) return;                              // warp-uniform exit
    const int nsamp = min(SPW, B - sbase);

    float* sw = s_buf + w * FPW;

    // ---- stage gmem -> smem (per-warp, coalesced, async) ----
    if (nsamp == SPW) {
        // 1440 floats = 360 float4: 11 full rounds + 8 lanes
        const char* gsrc = reinterpret_cast<const char*>(in + (size_t)sbase * 45);
        uint32_t sdst = (uint32_t)__cvta_generic_to_shared(sw);
        #pragma unroll
        for (int j = 0; j < 11; j++) {
            const int i = lane + 32 * j;
            cp_async16(sdst + i * 16, gsrc + i * 16);
        }
        if (lane < 8) {
            const int i = lane + 352;
            cp_async16(sdst + i * 16, gsrc + i * 16);
        }
        asm volatile("cp.async.commit_group;\n"
                     "cp.async.wait_group 0;" ::: "memory");
    } else {
        const size_t goff = (size_t)sbase * 45;
        for (int i = lane; i < nsamp * 45; i += 32) sw[i] = in[goff + i];
    }
    __syncwarp();

    // ---- compute: one sample per lane, straight from smem ----
    float r[15];
    if (lane < nsamp) {
        const float* __restrict__ p = sw + lane * 45;    // stride 45 odd -> conflict-free
        const int conn[15] = {0, 0, 1, 1, 1, 3, 4, 5, 6, 2, 2, 9, 10, 11, 12};
        #pragma unroll
        for (int k = 0; k < 15; k++) {
            const int c = conn[k];                       // compile-time constant
            const float dx = p[3 * k + 0] - p[3 * c + 0];
            const float dy = p[3 * k + 1] - p[3 * c + 1];
            const float dz = p[3 * k + 2] - p[3 * c + 2];
            r[k] = fast_sqrt(dx * dx + dy * dy + dz * dz);
        }
    }
    __syncwarp();                    // all smem reads done before overwrite

    if (lane < nsamp) {
        float* q = sw + lane * 15;                       // stride 15 odd -> conflict-free
        #pragma unroll
        for (int k = 0; k < 15; k++) q[k] = r[k];
    }
    __syncwarp();

    // ---- coalesced store: smem -> gmem (nsamp*15 floats) ----
    {
        const size_t goff = (size_t)sbase * 15;
        const int nfloat = nsamp * 15;
        const int n4 = nfloat >> 2;                      // 120 when full
        float4* __restrict__ g4 = reinterpret_cast<float4*>(out + goff);
        const float4* s4 = reinterpret_cast<const float4*>(sw);
        #pragma unroll 4
        for (int i = lane; i < n4; i += 32) g4[i] = s4[i];
        for (int i = (n4 << 2) + lane; i < nfloat; i += 32)
            out[goff + i] = sw[i];
    }
}

extern "C" void kernel_launch(void* const* d_in, const int* in_sizes, int n_in,
                              void* d_out, int out_size) {
    const float* in = (const float*)d_in[0];
    float* out = (float*)d_out;
    const int B = in_sizes[0] / 45;
    const int spb = WARPS * SPW;     // 96 samples per block
    const int grid = (B + spb - 1) / spb;
    limb_length_kernel<<<grid, TPB>>>(in, out, B);
}